// round 16
// baseline (speedup 1.0000x reference)
#include <cuda_runtime.h>
#include <cuda_fp16.h>
#include <cstdint>

#define DEV_INLINE __device__ __forceinline__

// ------------- device-global scratch -------------
static __device__ __half g_G[2ULL * 512 * 64 * 2048];   // gate preactivations fp16 [d][T][B][4H]
static __device__ __half g_h1[512 * 64 * 1024];         // layer-0 output [T][B][2H] fp16
static __device__ __half g_h2[512 * 64 * 1024];         // layer-1 output fp16
static __device__ __half g_xh[64 * 512 * 168];          // fp16 x
static __device__ __half g_w0h[2 * 2048 * 168];
static __device__ __half g_w1h[2 * 2048 * 1024];
static __device__ __half g_woh[168 * 1024];
static __device__ __half g_hbuf[2][2][2][64][512];      // [layer][dir][parity][b][k] fp16 h
static __device__ int    g_bar[8][256];                 // [layer*4+d*2+bh][cta*8] flags

// ------------- helpers -------------
DEV_INLINE unsigned sptr(const void* p) { return (unsigned)__cvta_generic_to_shared(p); }

DEV_INLINE void cp16(void* d, const void* s, int bytes) {
    asm volatile("cp.async.cg.shared.global [%0],[%1],16,%2;\n"
                 :: "r"(sptr(d)), "l"(s), "r"(bytes));
}
DEV_INLINE void cp_commit() { asm volatile("cp.async.commit_group;\n"); }
DEV_INLINE void cp_wait0()  { asm volatile("cp.async.wait_group 0;\n"); }
DEV_INLINE void cp_wait2()  { asm volatile("cp.async.wait_group 2;\n"); }

DEV_INLINE void mmah(float c[4], unsigned a0, unsigned a1, unsigned a2, unsigned a3,
                     unsigned b0, unsigned b1) {
    asm volatile("mma.sync.aligned.m16n8k16.row.col.f32.f16.f16.f32 "
                 "{%0,%1,%2,%3},{%4,%5,%6,%7},{%8,%9},{%0,%1,%2,%3};"
                 : "+f"(c[0]), "+f"(c[1]), "+f"(c[2]), "+f"(c[3])
                 : "r"(a0), "r"(a1), "r"(a2), "r"(a3), "r"(b0), "r"(b1));
}

DEV_INLINE void ldsm4(unsigned& a0, unsigned& a1, unsigned& a2, unsigned& a3, unsigned addr) {
    asm volatile("ldmatrix.sync.aligned.m8n8.x4.shared.b16 {%0,%1,%2,%3},[%4];"
                 : "=r"(a0), "=r"(a1), "=r"(a2), "=r"(a3) : "r"(addr));
}

DEV_INLINE int ld_acq(const int* p) {
    int v;
    asm volatile("ld.acquire.gpu.global.b32 %0,[%1];" : "=r"(v) : "l"(p) : "memory");
    return v;
}
DEV_INLINE void st_rel(int* p, int v) {
    asm volatile("st.release.gpu.global.b32 [%0],%1;" :: "l"(p), "r"(v) : "memory");
}
DEV_INLINE int ld_acq_sh(const int* p) {
    int v;
    asm volatile("ld.acquire.cta.shared.b32 %0,[%1];" : "=r"(v) : "r"(sptr(p)) : "memory");
    return v;
}
DEV_INLINE void st_rel_sh(int* p, int v) {
    asm volatile("st.release.cta.shared.b32 [%0],%1;" :: "r"(sptr(p)), "r"(v) : "memory");
}

DEV_INLINE float sigm(float x)   { return 1.0f / (1.0f + __expf(-x)); }
DEV_INLINE float tanh_f(float x) { float e = __expf(2.0f * x); return 1.0f - 2.0f / (e + 1.0f); }

// ------------- fp16 pre-rounding -------------
__global__ void round_all_k(const float* __restrict__ x,  const float* __restrict__ w0,
                            const float* __restrict__ w1, const float* __restrict__ wo) {
    const int N0 = 64 * 512 * 168;
    const int N1 = 2 * 2048 * 168;
    const int N2 = 2 * 2048 * 1024;
    const int N3 = 168 * 1024;
    int total = N0 + N1 + N2 + N3;
    for (int i = blockIdx.x * blockDim.x + threadIdx.x; i < total; i += gridDim.x * blockDim.x) {
        if (i < N0)                 g_xh[i] = __float2half_rn(x[i]);
        else if (i < N0 + N1)       g_w0h[i - N0] = __float2half_rn(w0[i - N0]);
        else if (i < N0 + N1 + N2)  g_w1h[i - N0 - N1] = __float2half_rn(w1[i - N0 - N1]);
        else                        g_woh[i - N0 - N1 - N2] = __float2half_rn(wo[i - N0 - N1 - N2]);
    }
}

__global__ void reset_k() {
    int gt = blockIdx.x * 256 + threadIdx.x;
    if (gt < 8 * 256) ((int*)g_bar)[gt] = 0;
    unsigned* hb = (unsigned*)&g_hbuf[0][0][0][0][0];   // 524288 halves = 262144 u32
    for (int i = gt; i < 262144; i += 64 * 256) hb[i] = 0u;
}

// ------------- fp16 GEMM, 4-stage cp.async pipeline, ldmatrix operands --------
template <bool HALF_OUT>
__global__ void __launch_bounds__(256, 2)
gemm_k(const __half* __restrict__ A, const __half* __restrict__ W,
       const float* __restrict__ bias, void* __restrict__ Cv,
       int M, int N, int K, int DIV, long long S1, long long S2, long long S3) {
    extern __shared__ char gsm[];
    char* Asm = gsm;                 // 4 stages x 128 rows x 80B = 40960
    char* Bsm = gsm + 40960;         // 4 stages x  64 rows x 80B = 20480

    int tid = threadIdx.x, lane = tid & 31, wid = tid >> 5;
    int wm = wid & 3, wn = wid >> 2;
    int mbase = blockIdx.y * 128, nbase = blockIdx.x * 64;
    int KT = (K + 31) >> 5;

    float acc[2][4][4];
#pragma unroll
    for (int mt = 0; mt < 2; mt++)
#pragma unroll
        for (int nt = 0; nt < 4; nt++)
#pragma unroll
            for (int e = 0; e < 4; e++) acc[mt][nt][e] = 0.0f;

    auto load_stage = [&](int kt) {
        int s = kt & 3;
        int k0 = kt * 32;
        char* as = Asm + s * 10240;
        char* bs = Bsm + s * 5120;
#pragma unroll
        for (int i = 0; i < 2; i++) {
            int ch = i * 256 + tid;
            int row = ch >> 2, seg = ch & 3;
            int k = k0 + seg * 8;
            int el = K - k; if (el > 8) el = 8; if (el < 0) el = 0;
            int bytes = el * 2;
            const __half* src = A + (size_t)(mbase + row) * K + (bytes ? k : 0);
            cp16(as + row * 80 + seg * 16, src, bytes);
        }
        {
            int row = tid >> 2, seg = tid & 3;
            int k = k0 + seg * 8;
            int n = nbase + row;
            int el = K - k; if (el > 8) el = 8; if (el < 0) el = 0;
            int bytes = el * 2;
            if (n >= N) bytes = 0;
            const __half* src = (bytes ? (W + (size_t)n * K + k) : W);
            cp16(bs + row * 80 + seg * 16, src, bytes);
        }
        cp_commit();
    };

    load_stage(0);
    if (KT > 1) load_stage(1);
    if (KT > 2) load_stage(2);

    const int lt = lane >> 3, lr = lane & 7;
    const unsigned l_off = (unsigned)(((lt & 1) * 8 + lr) * 80 + (lt >> 1) * 16);

    for (int kt = 0; kt < KT; kt++) {
        cp_wait2();
        __syncthreads();
        if (kt + 3 < KT) load_stage(kt + 3);
        unsigned as = sptr(Asm + (kt & 3) * 10240);
        unsigned bs = sptr(Bsm + (kt & 3) * 5120);
#pragma unroll
        for (int kg = 0; kg < 2; kg++) {
            unsigned a[2][4], b[2][4];
#pragma unroll
            for (int mt = 0; mt < 2; mt++)
                ldsm4(a[mt][0], a[mt][1], a[mt][2], a[mt][3],
                      as + (unsigned)((wm * 32 + mt * 16) * 80 + kg * 32) + l_off);
#pragma unroll
            for (int ntp = 0; ntp < 2; ntp++)
                ldsm4(b[ntp][0], b[ntp][1], b[ntp][2], b[ntp][3],
                      bs + (unsigned)((wn * 32 + ntp * 16) * 80 + kg * 32) + l_off);
#pragma unroll
            for (int mt = 0; mt < 2; mt++)
#pragma unroll
                for (int ntp = 0; ntp < 2; ntp++) {
                    mmah(acc[mt][ntp * 2],     a[mt][0], a[mt][1], a[mt][2], a[mt][3],
                         b[ntp][0], b[ntp][2]);
                    mmah(acc[mt][ntp * 2 + 1], a[mt][0], a[mt][1], a[mt][2], a[mt][3],
                         b[ntp][1], b[ntp][3]);
                }
        }
    }

#pragma unroll
    for (int mt = 0; mt < 2; mt++) {
#pragma unroll
        for (int nt = 0; nt < 4; nt++) {
            int m0 = mbase + wm * 32 + mt * 16 + (lane >> 2);
            int n0 = nbase + wn * 32 + nt * 8 + 2 * (lane & 3);
            if (n0 < N) {
                float bv0 = bias[n0], bv1 = bias[n0 + 1];
                long long nb = (long long)(n0 >> 11) * S3 + (n0 & 2047);
                long long o0 = (long long)(m0 / DIV) * S1 + (long long)(m0 % DIV) * S2 + nb;
                int m1 = m0 + 8;
                long long o1 = (long long)(m1 / DIV) * S1 + (long long)(m1 % DIV) * S2 + nb;
                if (HALF_OUT) {
                    __half* C = (__half*)Cv;
                    *(__half2*)(C + o0) = __floats2half2_rn(acc[mt][nt][0] + bv0, acc[mt][nt][1] + bv1);
                    *(__half2*)(C + o1) = __floats2half2_rn(acc[mt][nt][2] + bv0, acc[mt][nt][3] + bv1);
                } else {
                    float* C = (float*)Cv;
                    *(float2*)(C + o0) = make_float2(acc[mt][nt][0] + bv0, acc[mt][nt][1] + bv1);
                    *(float2*)(C + o1) = make_float2(acc[mt][nt][2] + bv0, acc[mt][nt][3] + bv1);
                }
            }
        }
    }
}

// ------------- persistent bidirectional LSTM recurrence, per-chunk dataflow ---
// grid 128 (d, bh, ncta), 256 threads = 8 warps (wm2 x wn4, m16 x n16 tiles).
// R16: warp w OWNS chunk w (k = 64w..64w+63): polls its 4 producer CTAs,
// stages its 4KB chunk, publishes an SMEM token. Consumers spin on tokens
// (LDS acquire) -> stragglers delay one chunk, not the whole step.
// Compute arithmetic identical to R15 -> rel_err must be exactly 3.836888e-4.
__global__ void __launch_bounds__(256, 1)
lstm_k(const float* __restrict__ Whh, const __half* __restrict__ G,
       __half* __restrict__ hout, int layer) {
    extern __shared__ char smc[];
    unsigned* bfu = (unsigned*)smc;                 // 65536B weight frags
    char*   hsb = smc + 65536;                      // 8 chunk bufs x 4608B = 36864
    __half* Gs  = (__half*)(smc + 65536 + 36864);   // 32 x 64 halves = 4096B
    float*  dmp = (float*)(smc + 65536 + 36864 + 4096); // 32 x 68 floats = 8704B
    int*    tok = (int*)(smc + 65536 + 36864 + 4096 + 8704); // 8 tokens, stride 16 ints

    const int tid = threadIdx.x;
    const int lane = tid & 31, wid = tid >> 5;
    const int wm = wid & 1;
    const int wn = wid >> 1;
    const int d = blockIdx.x >> 6;
    const int bh = (blockIdx.x >> 5) & 1;
    const int ncta = blockIdx.x & 31;
    const int jbase = ncta * 16;
    int* bar = &g_bar[layer * 4 + d * 2 + bh][0];

    if (tid < 8) tok[tid * 16] = -1;

    // ---- preload Whh slice (64 rows x 512) into fp16 fragment-packed SMEM ----
    const float* Wd = Whh + (size_t)d * 2048 * 512;
    __half* bfh = (__half*)bfu;
    for (int idx = tid; idx < 64 * 512; idx += 256) {
        int ns = idx >> 9, k = idx & 511;
        int grow = (ns & 3) * 512 + jbase + (ns >> 2);   // gate*512 + unit
        __half v = __float2half_rn(Wd[(size_t)grow * 512 + k]);
        int wnn = ns >> 4;
        int r = ns & 15;
        int nt = r >> 3, col = r & 7;
        int cc = k >> 6, kg = (k >> 4) & 3, ki = k & 15;
        int breg = ki >> 3;
        int ln = (col << 2) | ((ki & 7) >> 1);
        int hidx = ki & 1;
        int slot = nt * 2 + breg;
        int b32idx = (((wnn * 8 + cc) * 4 + kg) * 32 + ln) * 4 + slot;
        bfh[b32idx * 2 + hidx] = v;
    }
    __syncthreads();

    const __half* Gbase = G + (size_t)d * 512 * 64 * 2048;
    float cst[2];
    cst[0] = 0.0f; cst[1] = 0.0f;
    const int b_ep = tid >> 3;           // local batch 0..31
    const int uoff = (tid & 7) * 2;      // unit pair

    const int arow = wm * 16 + ((lane >> 3) & 1) * 8 + (lane & 7);
    const int akoff = ((lane >> 4) & 1) * 16;        // bytes
    const unsigned hs_addr = sptr(hsb);

    for (int t = 0; t < 512; t++) {
        int tt = d ? (511 - t) : t;

        // stage gate preactivations (fp16, 1 cp16/thread, no cross-CTA dep)
        const __half* Gp = Gbase + (size_t)tt * 64 * 2048 + (size_t)(bh * 32) * 2048;
        {
            int b = tid >> 3, g = (tid >> 1) & 3, part = tid & 1;
            cp16(Gs + b * 64 + g * 16 + part * 8,
                 Gp + (size_t)b * 2048 + g * 512 + jbase + part * 8, 16);
        }
        cp_commit();

        // warp wid polls ONLY its chunk's 4 producer CTAs (4*wid..4*wid+3)
        if (t > 0) {
            for (;;) {
                int v = t;
                if (lane < 4) v = ld_acq(&bar[(wid * 4 + lane) * 8]);
                if (__all_sync(0xffffffffu, v >= t)) break;
            }
        }

        // stage own chunk (32 batches x 64 halves = 4KB, 8 cp16/lane)
        {
            const char* hsrc = (const char*)&g_hbuf[layer][d][(t + 1) & 1][bh * 32][0];
            char* dst = hsb + wid * 4608;
#pragma unroll
            for (int i = 0; i < 8; i++) {
                int s = lane * 8 + i;            // 0..255
                int b = s >> 3, seg = s & 7;
                cp16(dst + b * 144 + seg * 16,
                     hsrc + (size_t)b * 1024 + wid * 128 + seg * 16, 16);
            }
            cp_commit();
        }
        cp_wait0();          // drains Gs + own chunk (this thread's groups)
        __syncwarp();        // memory-order all lanes' copies before the token
        if (lane == 0) st_rel_sh(&tok[wid * 16], t);

        float acc[2][4];
#pragma unroll
        for (int nt = 0; nt < 2; nt++)
#pragma unroll
            for (int e = 0; e < 4; e++) acc[nt][e] = 0.0f;

#pragma unroll
        for (int c = 0; c < 8; c++) {
            // wait for chunk c's token (SMEM acquire spin, ~30cyc per check)
            if (lane == 0) {
                while (ld_acq_sh(&tok[c * 16]) < t) {}
            }
            __syncwarp();

            unsigned habase = hs_addr + c * 4608 + arow * 144 + akoff;
            const uint4* bb = (const uint4*)(bfu + (((wn * 8 + c) * 4) * 32 + lane) * 4);
#pragma unroll
            for (int g = 0; g < 4; g++) {
                unsigned a0, a1, a2, a3;
                ldsm4(a0, a1, a2, a3, habase + g * 32);
                uint4 bv = bb[g * 32];
                mmah(acc[0], a0, a1, a2, a3, bv.x, bv.y);
                mmah(acc[1], a0, a1, a2, a3, bv.z, bv.w);
            }
        }

        // dump gates to SMEM for the cross-thread transpose (m 0..31, n 0..63)
#pragma unroll
        for (int nt = 0; nt < 2; nt++) {
            int m0 = wm * 16 + (lane >> 2);
            int n0 = wn * 16 + nt * 8 + 2 * (lane & 3);
            dmp[m0 * 68 + n0]           = acc[nt][0];
            dmp[m0 * 68 + n0 + 1]       = acc[nt][1];
            dmp[(m0 + 8) * 68 + n0]     = acc[nt][2];
            dmp[(m0 + 8) * 68 + n0 + 1] = acc[nt][3];
        }
        __syncthreads();

        // epilogue: thread handles local batch b_ep, units uoff, uoff+1
        __half hh[2];
#pragma unroll
        for (int i = 0; i < 2; i++) {
            int u = uoff + i;
            float gi = dmp[b_ep * 68 + u * 4 + 0] + __half2float(Gs[b_ep * 64 + 0 * 16 + u]);
            float gf = dmp[b_ep * 68 + u * 4 + 1] + __half2float(Gs[b_ep * 64 + 1 * 16 + u]);
            float gg = dmp[b_ep * 68 + u * 4 + 2] + __half2float(Gs[b_ep * 64 + 2 * 16 + u]);
            float go = dmp[b_ep * 68 + u * 4 + 3] + __half2float(Gs[b_ep * 64 + 3 * 16 + u]);
            float cv = sigm(gf) * cst[i] + sigm(gi) * tanh_f(gg);
            cst[i] = cv;
            hh[i] = __float2half_rn(sigm(go) * tanh_f(cv));
        }

        int bglob = bh * 32 + b_ep;
        __half2 hv = __halves2half2(hh[0], hh[1]);
        *(__half2*)&g_hbuf[layer][d][t & 1][bglob][jbase + uoff] = hv;

        __syncthreads();   // orders all threads' g_hbuf writes + Gs/dmp/hsb WAR
        if (tid == 0 && t < 511) st_rel(&bar[ncta * 8], t + 1);

        // hout consumed only by the NEXT kernel launch -> off the critical path
        *(__half2*)(hout + ((size_t)tt * 64 + bglob) * 1024 + d * 512 + jbase + uoff) = hv;
    }
}

// ------------- host launcher -------------
extern "C" void kernel_launch(void* const* d_in, const int* in_sizes, int n_in,
                              void* d_out, int out_size) {
    (void)in_sizes; (void)n_in; (void)out_size;
    const float* Whh0 = (const float*)d_in[2];
    const float* b0   = (const float*)d_in[3];
    const float* Whh1 = (const float*)d_in[5];
    const float* b1   = (const float*)d_in[6];
    const float* bout = (const float*)d_in[8];
    float* out = (float*)d_out;

    const int LSMEM = 65536 + 36864 + 4096 + 8704 + 512;  // 115712
    const int GSMEM = 40960 + 20480;                      // 61440
    cudaFuncSetAttribute(lstm_k, cudaFuncAttributeMaxDynamicSharedMemorySize, LSMEM);
    cudaFuncSetAttribute(gemm_k<true>,  cudaFuncAttributeMaxDynamicSharedMemorySize, GSMEM);
    cudaFuncSetAttribute(gemm_k<false>, cudaFuncAttributeMaxDynamicSharedMemorySize, GSMEM);

    __half *xh, *w0h, *w1h, *woh, *h1, *h2, *G;
    cudaGetSymbolAddress((void**)&xh,  g_xh);
    cudaGetSymbolAddress((void**)&w0h, g_w0h);
    cudaGetSymbolAddress((void**)&w1h, g_w1h);
    cudaGetSymbolAddress((void**)&woh, g_woh);
    cudaGetSymbolAddress((void**)&G,   g_G);
    cudaGetSymbolAddress((void**)&h1,  g_h1);
    cudaGetSymbolAddress((void**)&h2,  g_h2);

    const long long GSZ = 512LL * 64 * 2048;

    reset_k<<<64, 256>>>();
    round_all_k<<<2048, 256>>>((const float*)d_in[0], (const float*)d_in[1],
                               (const float*)d_in[4], (const float*)d_in[7]);

    // layer-0 input GEMM, both directions fused on N (N=4096, K=168) -> fp16 G
    gemm_k<true><<<dim3(64, 256), 256, GSMEM>>>(xh, w0h, b0, G,
                                                32768, 4096, 168, 512, 2048LL, 131072LL, GSZ);
    lstm_k<<<128, 256, LSMEM>>>(Whh0, G, h1, 0);

    // layer-1 input GEMM (N=4096, K=1024) -> fp16 G
    gemm_k<true><<<dim3(64, 256), 256, GSMEM>>>(h1, w1h, b1, G,
                                                32768, 4096, 1024, 64, 131072LL, 2048LL, GSZ);
    lstm_k<<<128, 256, LSMEM>>>(Whh1, G, h2, 1);

    // output projection (N=168, K=1024) -> fp32 out
    gemm_k<false><<<dim3(3, 256), 256, GSMEM>>>(h2, woh, bout, out,
                                                32768, 168, 1024, 64, 168LL, 86016LL, 0LL);
}

// round 17
// speedup vs baseline: 1.3316x; 1.3316x over previous
#include <cuda_runtime.h>
#include <cuda_fp16.h>
#include <cstdint>

#define DEV_INLINE __device__ __forceinline__

// ------------- device-global scratch -------------
static __device__ float  g_G[2ULL * 512 * 64 * 2048];   // gate preactivations [d][T][B][4H]
static __device__ __half g_h1[512 * 64 * 1024];         // layer-0 output [T][B][2H] fp16
static __device__ __half g_h2[512 * 64 * 1024];         // layer-1 output fp16
static __device__ __half g_xh[64 * 512 * 168];          // fp16 x
static __device__ __half g_w0h[2 * 2048 * 168];
static __device__ __half g_w1h[2 * 2048 * 1024];
static __device__ __half g_woh[168 * 1024];
static __device__ __half g_hbuf[2][2][2][64][512];      // [layer][dir][parity][b][k] fp16 h
static __device__ int    g_cnt[8][32];                  // per-chain arrival counter (128B apart)

// ------------- helpers -------------
DEV_INLINE unsigned sptr(const void* p) { return (unsigned)__cvta_generic_to_shared(p); }

DEV_INLINE void cp16(void* d, const void* s, int bytes) {
    asm volatile("cp.async.cg.shared.global [%0],[%1],16,%2;\n"
                 :: "r"(sptr(d)), "l"(s), "r"(bytes));
}
DEV_INLINE void cp_commit() { asm volatile("cp.async.commit_group;\n"); }
DEV_INLINE void cp_wait0()  { asm volatile("cp.async.wait_group 0;\n"); }
DEV_INLINE void cp_wait2()  { asm volatile("cp.async.wait_group 2;\n"); }

DEV_INLINE void mmah(float c[4], unsigned a0, unsigned a1, unsigned a2, unsigned a3,
                     unsigned b0, unsigned b1) {
    asm volatile("mma.sync.aligned.m16n8k16.row.col.f32.f16.f16.f32 "
                 "{%0,%1,%2,%3},{%4,%5,%6,%7},{%8,%9},{%0,%1,%2,%3};"
                 : "+f"(c[0]), "+f"(c[1]), "+f"(c[2]), "+f"(c[3])
                 : "r"(a0), "r"(a1), "r"(a2), "r"(a3), "r"(b0), "r"(b1));
}

DEV_INLINE void ldsm4(unsigned& a0, unsigned& a1, unsigned& a2, unsigned& a3, unsigned addr) {
    asm volatile("ldmatrix.sync.aligned.m8n8.x4.shared.b16 {%0,%1,%2,%3},[%4];"
                 : "=r"(a0), "=r"(a1), "=r"(a2), "=r"(a3) : "r"(addr));
}

DEV_INLINE int ld_acq(const int* p) {
    int v;
    asm volatile("ld.acquire.gpu.global.b32 %0,[%1];" : "=r"(v) : "l"(p) : "memory");
    return v;
}
DEV_INLINE void red_add_rel(int* p) {
    asm volatile("red.release.gpu.global.add.u32 [%0],%1;" :: "l"(p), "r"(1) : "memory");
}

DEV_INLINE float sigm(float x)   { return 1.0f / (1.0f + __expf(-x)); }
DEV_INLINE float tanh_f(float x) { float e = __expf(2.0f * x); return 1.0f - 2.0f / (e + 1.0f); }

// ------------- fp16 pre-rounding -------------
__global__ void round_all_k(const float* __restrict__ x,  const float* __restrict__ w0,
                            const float* __restrict__ w1, const float* __restrict__ wo) {
    const int N0 = 64 * 512 * 168;
    const int N1 = 2 * 2048 * 168;
    const int N2 = 2 * 2048 * 1024;
    const int N3 = 168 * 1024;
    int total = N0 + N1 + N2 + N3;
    for (int i = blockIdx.x * blockDim.x + threadIdx.x; i < total; i += gridDim.x * blockDim.x) {
        if (i < N0)                 g_xh[i] = __float2half_rn(x[i]);
        else if (i < N0 + N1)       g_w0h[i - N0] = __float2half_rn(w0[i - N0]);
        else if (i < N0 + N1 + N2)  g_w1h[i - N0 - N1] = __float2half_rn(w1[i - N0 - N1]);
        else                        g_woh[i - N0 - N1 - N2] = __float2half_rn(wo[i - N0 - N1 - N2]);
    }
}

__global__ void reset_k() {
    int gt = blockIdx.x * 256 + threadIdx.x;
    if (gt < 8 * 32) ((int*)g_cnt)[gt] = 0;
    unsigned* hb = (unsigned*)&g_hbuf[0][0][0][0][0];   // 524288 halves = 262144 u32
    for (int i = gt; i < 262144; i += 64 * 256) hb[i] = 0u;
}

// ------------- fp16 GEMM, 4-stage cp.async pipeline, ldmatrix operands --------
// C[m,n] = sum_k A[m,k]*W[n,k] + bias[n].  A,W fp16 row-major; C fp32.
// tile 128(M) x 64(N), k-tile 32, 256 threads (warps 4m x 2n, warp m32 x n32)
// out offset = (m/DIV)*S1 + (m%DIV)*S2 + (n>>11)*S3 + (n&2047)
__global__ void __launch_bounds__(256, 2)
gemm_k(const __half* __restrict__ A, const __half* __restrict__ W,
       const float* __restrict__ bias, float* __restrict__ C,
       int M, int N, int K, int DIV, long long S1, long long S2, long long S3) {
    extern __shared__ char gsm[];
    char* Asm = gsm;                 // 4 stages x 128 rows x 80B = 40960
    char* Bsm = gsm + 40960;         // 4 stages x  64 rows x 80B = 20480

    int tid = threadIdx.x, lane = tid & 31, wid = tid >> 5;
    int wm = wid & 3, wn = wid >> 2;
    int mbase = blockIdx.y * 128, nbase = blockIdx.x * 64;
    int KT = (K + 31) >> 5;

    float acc[2][4][4];
#pragma unroll
    for (int mt = 0; mt < 2; mt++)
#pragma unroll
        for (int nt = 0; nt < 4; nt++)
#pragma unroll
            for (int e = 0; e < 4; e++) acc[mt][nt][e] = 0.0f;

    auto load_stage = [&](int kt) {
        int s = kt & 3;
        int k0 = kt * 32;
        char* as = Asm + s * 10240;
        char* bs = Bsm + s * 5120;
#pragma unroll
        for (int i = 0; i < 2; i++) {
            int ch = i * 256 + tid;
            int row = ch >> 2, seg = ch & 3;
            int k = k0 + seg * 8;
            int el = K - k; if (el > 8) el = 8; if (el < 0) el = 0;
            int bytes = el * 2;
            const __half* src = A + (size_t)(mbase + row) * K + (bytes ? k : 0);
            cp16(as + row * 80 + seg * 16, src, bytes);
        }
        {
            int row = tid >> 2, seg = tid & 3;
            int k = k0 + seg * 8;
            int n = nbase + row;
            int el = K - k; if (el > 8) el = 8; if (el < 0) el = 0;
            int bytes = el * 2;
            if (n >= N) bytes = 0;
            const __half* src = (bytes ? (W + (size_t)n * K + k) : W);
            cp16(bs + row * 80 + seg * 16, src, bytes);
        }
        cp_commit();
    };

    load_stage(0);
    if (KT > 1) load_stage(1);
    if (KT > 2) load_stage(2);

    const int lt = lane >> 3, lr = lane & 7;
    const unsigned l_off = (unsigned)(((lt & 1) * 8 + lr) * 80 + (lt >> 1) * 16);

    for (int kt = 0; kt < KT; kt++) {
        cp_wait2();
        __syncthreads();
        if (kt + 3 < KT) load_stage(kt + 3);
        unsigned as = sptr(Asm + (kt & 3) * 10240);
        unsigned bs = sptr(Bsm + (kt & 3) * 5120);
#pragma unroll
        for (int kg = 0; kg < 2; kg++) {
            unsigned a[2][4], b[2][4];
#pragma unroll
            for (int mt = 0; mt < 2; mt++)
                ldsm4(a[mt][0], a[mt][1], a[mt][2], a[mt][3],
                      as + (unsigned)((wm * 32 + mt * 16) * 80 + kg * 32) + l_off);
#pragma unroll
            for (int ntp = 0; ntp < 2; ntp++)
                ldsm4(b[ntp][0], b[ntp][1], b[ntp][2], b[ntp][3],
                      bs + (unsigned)((wn * 32 + ntp * 16) * 80 + kg * 32) + l_off);
#pragma unroll
            for (int mt = 0; mt < 2; mt++)
#pragma unroll
                for (int ntp = 0; ntp < 2; ntp++) {
                    mmah(acc[mt][ntp * 2],     a[mt][0], a[mt][1], a[mt][2], a[mt][3],
                         b[ntp][0], b[ntp][2]);
                    mmah(acc[mt][ntp * 2 + 1], a[mt][0], a[mt][1], a[mt][2], a[mt][3],
                         b[ntp][1], b[ntp][3]);
                }
        }
    }

#pragma unroll
    for (int mt = 0; mt < 2; mt++) {
#pragma unroll
        for (int nt = 0; nt < 4; nt++) {
            int m0 = mbase + wm * 32 + mt * 16 + (lane >> 2);
            int n0 = nbase + wn * 32 + nt * 8 + 2 * (lane & 3);
            if (n0 < N) {
                float bv0 = bias[n0], bv1 = bias[n0 + 1];
                long long nb = (long long)(n0 >> 11) * S3 + (n0 & 2047);
                long long o0 = (long long)(m0 / DIV) * S1 + (long long)(m0 % DIV) * S2 + nb;
                int m1 = m0 + 8;
                long long o1 = (long long)(m1 / DIV) * S1 + (long long)(m1 % DIV) * S2 + nb;
                *(float2*)(C + o0) = make_float2(acc[mt][nt][0] + bv0, acc[mt][nt][1] + bv1);
                *(float2*)(C + o1) = make_float2(acc[mt][nt][2] + bv0, acc[mt][nt][3] + bv1);
            }
        }
    }
}

// ------------- persistent bidirectional LSTM recurrence, fp16 mma (R14) -------
// grid 128 (d, bh, ncta), 256 threads = 8 warps (wm2 x wn4), depth-3 chunk
// pipeline (8 chunks of k=64). h/Whh fp16, A via ldmatrix.x4, B pre-packed,
// mma.m16n8k16, fp32 accumulate/epilogue; G fp32.
// R17: step barrier = ONE arrival counter per chain (red.release add) and a
// single-lane single-line acquire poll -> 32x less flag traffic than R14.
__global__ void __launch_bounds__(256, 1)
lstm_k(const float* __restrict__ Whh, const float* __restrict__ G,
       __half* __restrict__ hout, int layer) {
    extern __shared__ char smc[];
    unsigned* bfu = (unsigned*)smc;                 // 16384 u32 = 64KB weight frags
    char*  hsb = smc + 65536;                       // 4 bufs x 32 rows x 144B = 18432B
    float* Gs  = (float*)(smc + 65536 + 18432);     // 32 x 64 floats
    float* dmp = (float*)(smc + 65536 + 18432 + 8192); // 32 x 68 floats

    const int tid = threadIdx.x;
    const int lane = tid & 31, wid = tid >> 5;
    const int wm = wid & 1;
    const int wn = wid >> 1;
    const int d = blockIdx.x >> 6;
    const int bh = (blockIdx.x >> 5) & 1;
    const int ncta = blockIdx.x & 31;
    const int jbase = ncta * 16;
    int* cnt = &g_cnt[layer * 4 + d * 2 + bh][0];

    // ---- preload Whh slice (64 rows x 512) into fp16 fragment-packed SMEM ----
    const float* Wd = Whh + (size_t)d * 2048 * 512;
    __half* bfh = (__half*)bfu;
    for (int idx = tid; idx < 64 * 512; idx += 256) {
        int ns = idx >> 9, k = idx & 511;
        int grow = (ns & 3) * 512 + jbase + (ns >> 2);   // gate*512 + unit
        __half v = __float2half_rn(Wd[(size_t)grow * 512 + k]);
        int wnn = ns >> 4;
        int r = ns & 15;
        int nt = r >> 3, col = r & 7;
        int cc = k >> 6, kg = (k >> 4) & 3, ki = k & 15;
        int breg = ki >> 3;
        int ln = (col << 2) | ((ki & 7) >> 1);
        int hidx = ki & 1;
        int slot = nt * 2 + breg;
        int b32idx = (((wnn * 8 + cc) * 4 + kg) * 32 + ln) * 4 + slot;
        bfh[b32idx * 2 + hidx] = v;
    }
    __syncthreads();

    const float* Gbase = G + (size_t)d * 512 * 64 * 2048;
    float cst[2];
    cst[0] = 0.0f; cst[1] = 0.0f;
    const int b_ep = tid >> 3;           // local batch 0..31
    const int uoff = (tid & 7) * 2;      // unit pair

    const int arow = wm * 16 + ((lane >> 3) & 1) * 8 + (lane & 7);
    const int akoff = ((lane >> 4) & 1) * 16;        // bytes
    const unsigned hs_addr = sptr(hsb);

    for (int t = 0; t < 512; t++) {
        int tt = d ? (511 - t) : t;

        // stage gate preactivations (fp32, no dependency on other CTAs)
        const float* Gp = Gbase + (size_t)tt * 64 * 2048 + (size_t)(bh * 32) * 2048;
#pragma unroll
        for (int i = 0; i < 2; i++) {
            int s = tid * 2 + i;
            int b = s >> 4, g = (s >> 2) & 3, part = s & 3;
            cp16(Gs + b * 64 + g * 16 + part * 4,
                 Gp + (size_t)b * 2048 + g * 512 + jbase + part * 4, 16);
        }
        cp_commit();

        // wait for all 32 CTAs of this chain to have arrived for step t-1:
        // single lane polling a single cache line
        if (t > 0 && tid == 0) {
            while (ld_acq(cnt) < 32 * t) {}
        }
        __syncthreads();

        const char* hsrc = (const char*)&g_hbuf[layer][d][(t + 1) & 1][bh * 32][0];

        // stage one 64-wide fp16 k-chunk for 32 batches (4KB, 1 cp16/thread)
        auto stage = [&](int c) {
            int b = tid >> 3, seg = tid & 7;
            cp16(hsb + (c & 3) * 4608 + b * 144 + seg * 16,
                 hsrc + (size_t)b * 1024 + c * 128 + seg * 16, 16);
            cp_commit();
        };
        stage(0);
        stage(1);
        stage(2);

        float acc[2][4];
#pragma unroll
        for (int nt = 0; nt < 2; nt++)
#pragma unroll
            for (int e = 0; e < 4; e++) acc[nt][e] = 0.0f;

#pragma unroll
        for (int c = 0; c < 8; c++) {
            if (c < 6) cp_wait2(); else cp_wait0();
            __syncthreads();
            if (c < 5) stage(c + 3);

            unsigned habase = hs_addr + (c & 3) * 4608 + arow * 144 + akoff;
            const uint4* bb = (const uint4*)(bfu + (((wn * 8 + c) * 4) * 32 + lane) * 4);
#pragma unroll
            for (int g = 0; g < 4; g++) {
                unsigned a0, a1, a2, a3;
                ldsm4(a0, a1, a2, a3, habase + g * 32);
                uint4 bv = bb[g * 32];
                mmah(acc[0], a0, a1, a2, a3, bv.x, bv.y);
                mmah(acc[1], a0, a1, a2, a3, bv.z, bv.w);
            }
        }

        // dump gates to SMEM for the cross-thread transpose (m 0..31, n 0..63)
#pragma unroll
        for (int nt = 0; nt < 2; nt++) {
            int m0 = wm * 16 + (lane >> 2);
            int n0 = wn * 16 + nt * 8 + 2 * (lane & 3);
            dmp[m0 * 68 + n0]           = acc[nt][0];
            dmp[m0 * 68 + n0 + 1]       = acc[nt][1];
            dmp[(m0 + 8) * 68 + n0]     = acc[nt][2];
            dmp[(m0 + 8) * 68 + n0 + 1] = acc[nt][3];
        }
        __syncthreads();

        // epilogue: thread handles local batch b_ep, units uoff, uoff+1
        __half hh[2];
#pragma unroll
        for (int i = 0; i < 2; i++) {
            int u = uoff + i;
            float gi = dmp[b_ep * 68 + u * 4 + 0] + Gs[b_ep * 64 + 0 * 16 + u];
            float gf = dmp[b_ep * 68 + u * 4 + 1] + Gs[b_ep * 64 + 1 * 16 + u];
            float gg = dmp[b_ep * 68 + u * 4 + 2] + Gs[b_ep * 64 + 2 * 16 + u];
            float go = dmp[b_ep * 68 + u * 4 + 3] + Gs[b_ep * 64 + 3 * 16 + u];
            float cv = sigm(gf) * cst[i] + sigm(gi) * tanh_f(gg);
            cst[i] = cv;
            hh[i] = __float2half_rn(sigm(go) * tanh_f(cv));
        }

        int bglob = bh * 32 + b_ep;
        __half2 hv = __halves2half2(hh[0], hh[1]);
        *(__half2*)&g_hbuf[layer][d][t & 1][bglob][jbase + uoff] = hv;
        *(__half2*)(hout + ((size_t)tt * 64 + bglob) * 1024 + d * 512 + jbase + uoff) = hv;

        __syncthreads();   // orders all threads' g_hbuf writes + Gs/dmp/hsb WAR
        if (tid == 0 && t < 511) red_add_rel(cnt);   // one fire-and-forget arrival
    }
}

// ------------- host launcher -------------
extern "C" void kernel_launch(void* const* d_in, const int* in_sizes, int n_in,
                              void* d_out, int out_size) {
    (void)in_sizes; (void)n_in; (void)out_size;
    const float* Whh0 = (const float*)d_in[2];
    const float* b0   = (const float*)d_in[3];
    const float* Whh1 = (const float*)d_in[5];
    const float* b1   = (const float*)d_in[6];
    const float* bout = (const float*)d_in[8];
    float* out = (float*)d_out;

    const int LSMEM = 65536 + 18432 + 8192 + 8704;   // 100864
    const int GSMEM = 40960 + 20480;                 // 61440
    cudaFuncSetAttribute(lstm_k, cudaFuncAttributeMaxDynamicSharedMemorySize, LSMEM);
    cudaFuncSetAttribute(gemm_k, cudaFuncAttributeMaxDynamicSharedMemorySize, GSMEM);

    __half *xh, *w0h, *w1h, *woh, *h1, *h2;
    float *G;
    cudaGetSymbolAddress((void**)&xh,  g_xh);
    cudaGetSymbolAddress((void**)&w0h, g_w0h);
    cudaGetSymbolAddress((void**)&w1h, g_w1h);
    cudaGetSymbolAddress((void**)&woh, g_woh);
    cudaGetSymbolAddress((void**)&G,   g_G);
    cudaGetSymbolAddress((void**)&h1,  g_h1);
    cudaGetSymbolAddress((void**)&h2,  g_h2);

    const long long GSZ = 512LL * 64 * 2048;

    reset_k<<<64, 256>>>();
    round_all_k<<<2048, 256>>>((const float*)d_in[0], (const float*)d_in[1],
                               (const float*)d_in[4], (const float*)d_in[7]);

    // layer-0 input GEMM, both directions fused on N (N=4096, K=168)
    gemm_k<<<dim3(64, 256), 256, GSMEM>>>(xh, w0h, b0, G,
                                          32768, 4096, 168, 512, 2048LL, 131072LL, GSZ);
    lstm_k<<<128, 256, LSMEM>>>(Whh0, G, h1, 0);

    // layer-1 input GEMM (N=4096, K=1024)
    gemm_k<<<dim3(64, 256), 256, GSMEM>>>(h1, w1h, b1, G,
                                          32768, 4096, 1024, 64, 131072LL, 2048LL, GSZ);
    lstm_k<<<128, 256, LSMEM>>>(Whh1, G, h2, 1);

    // output projection (N=168, K=1024)
    gemm_k<<<dim3(3, 256), 256, GSMEM>>>(h2, woh, bout, out,
                                         32768, 168, 1024, 64, 168LL, 86016LL, 0LL);
}